// round 4
// baseline (speedup 1.0000x reference)
#include <cuda_runtime.h>
#include <cstdint>

// Problem shape (fixed per reference):
//   B=32, N=4096, E=8192, D=128
#define BB   32
#define NN   4096
#define EE   8192
#define DD   128
#define MM   (BB * NN)          // 131072 rows
#define NEDGE (BB * EE)         // 262144 edges

// device scratch (no runtime alloc): CSR + tf32 weights
__device__ int      g_cnt[MM];            // counts (self-zeroing via fill)
__device__ int      g_off[MM + 1];        // exclusive offsets
__device__ int      g_edge[NEDGE];        // edge ids bucketed by target node
__device__ uint32_t g_Btf[2 * 3 * 128 * 128];   // [m][q][k][c] chunk-major tf32

// ---------------------------------------------------------------------------
// helpers
// ---------------------------------------------------------------------------
__device__ __forceinline__ uint32_t f2tf32(float x) {
    uint32_t r;
    asm("cvt.rna.tf32.f32 %0, %1;" : "=r"(r) : "f"(x));
    return r;
}

__device__ __forceinline__ float sigmoidf_fast(float x) {
    return 1.0f / (1.0f + __expf(-x));
}

__device__ __forceinline__ float tanh_safe(float x) {
    float e = __expf(-2.0f * fabsf(x));
    float t = (1.0f - e) / (1.0f + e);
    return copysignf(t, x);
}

__device__ __forceinline__ void mma_tf32(float c[4], const uint32_t a[4], const uint32_t b[2]) {
    asm volatile(
        "mma.sync.aligned.m16n8k8.row.col.f32.tf32.tf32.f32 "
        "{%0,%1,%2,%3}, {%4,%5,%6,%7}, {%8,%9}, {%0,%1,%2,%3};\n"
        : "+f"(c[0]), "+f"(c[1]), "+f"(c[2]), "+f"(c[3])
        : "r"(a[0]), "r"(a[1]), "r"(a[2]), "r"(a[3]),
          "r"(b[0]), "r"(b[1]));
}

__device__ __forceinline__ void cp_async16(uint32_t smem_addr, const void* gptr) {
    asm volatile("cp.async.cg.shared.global [%0], [%1], 16;\n"
                 :: "r"(smem_addr), "l"(gptr));
}

// ---------------------------------------------------------------------------
// CSR build: histogram -> scan -> fill
// ---------------------------------------------------------------------------
__global__ void hist_kernel(const int* __restrict__ conn) {
    const int i = blockIdx.x * blockDim.x + threadIdx.x;
    if (i >= NEDGE) return;
    const int tgt = __ldg(&conn[2 * i + 1]);
    const int node = ((i >> 13) << 12) + tgt;     // b*NN + tgt
    atomicAdd(&g_cnt[node], 1);
}

__global__ void scan_kernel() {   // 1 block, 1024 threads, 128 elems/thread
    __shared__ int part[1024];
    const int t = threadIdx.x;
    int sum = 0;
#pragma unroll 4
    for (int k = 0; k < 128; k++) sum += g_cnt[t * 128 + k];
    part[t] = sum;
    __syncthreads();
#pragma unroll
    for (int d = 1; d < 1024; d <<= 1) {
        int v = (t >= d) ? part[t - d] : 0;
        __syncthreads();
        part[t] += v;
        __syncthreads();
    }
    int run = (t == 0) ? 0 : part[t - 1];
#pragma unroll 4
    for (int k = 0; k < 128; k++) {
        g_off[t * 128 + k] = run;
        run += g_cnt[t * 128 + k];
    }
    if (t == 1023) g_off[MM] = run;
}

__global__ void fill_kernel(const int* __restrict__ conn) {
    const int i = blockIdx.x * blockDim.x + threadIdx.x;
    if (i >= NEDGE) return;
    const int tgt = __ldg(&conn[2 * i + 1]);
    const int node = ((i >> 13) << 12) + tgt;
    const int pos = atomicSub(&g_cnt[node], 1) - 1;  // also restores g_cnt to 0
    g_edge[g_off[node] + pos] = i;
}

// ---------------------------------------------------------------------------
// convert W and U to chunk-major tf32 scratch
// ---------------------------------------------------------------------------
__global__ void convert_B_kernel(const float* __restrict__ W,
                                 const float* __restrict__ U) {
    const int idx = blockIdx.x * blockDim.x + threadIdx.x;   // x float4
    if (idx >= 2 * 3 * 128 * 32) return;
    const int c4   = (idx & 31) << 2;
    const int k    = (idx >> 5) & 127;
    const int rest = idx >> 12;          // 0..5
    const int m    = rest / 3;
    const int q    = rest % 3;
    const float* src = m ? U : W;
    float4 v = *reinterpret_cast<const float4*>(&src[k * 384 + q * 128 + c4]);
    uint4 t = make_uint4(f2tf32(v.x), f2tf32(v.y), f2tf32(v.z), f2tf32(v.w));
    *reinterpret_cast<uint4*>(&g_Btf[((m * 3 + q) * 128 + k) * 128 + c4]) = t;
}

// ---------------------------------------------------------------------------
// fused gather + dual-GEMM + GRU gates (cp.async double-buffered B pipeline)
// ---------------------------------------------------------------------------
#define SA_PAD 132
#define SB_PAD 136
#define SA_BYTES (64 * SA_PAD * 4)
#define SBBUF_BYTES (64 * SB_PAD * 4)
#define SMEM_BYTES (2 * SA_BYTES + 2 * SBBUF_BYTES)

__host__ __device__ constexpr int stage_gbase(int s) {
    int m = (s < 6) ? 0 : 1;
    int qi = (m == 0) ? (s >> 1) : ((s - 6) >> 1);
    int q = (m == 0) ? qi : (qi == 0 ? 1 : (qi == 1 ? 0 : 2));
    int h = s & 1;
    return ((m * 3 + q) * 128 + h * 64) * 128;
}

__device__ __forceinline__ void issue_load(uint32_t sdst, int gbase, int tid) {
#pragma unroll
    for (int i = 0; i < 8; i++) {
        const int idx = tid + i * 256;
        const int row = idx >> 5;
        const int c4  = (idx & 31) << 2;
        cp_async16(sdst + (uint32_t)(row * SB_PAD + c4) * 4,
                   &g_Btf[gbase + row * 128 + c4]);
    }
}

template <bool FROM_TF32>
__device__ __forceinline__ void compute_half(float* __restrict__ acc,
                                             const uint32_t* __restrict__ sA_t,
                                             const float*    __restrict__ sA_f,
                                             const uint32_t* __restrict__ sB,
                                             int kbase,
                                             int warpM, int warpN, int gID, int tig) {
#pragma unroll
    for (int ks = 0; ks < 8; ks++) {
        const int k0 = kbase + ks * 8;
        const int bk = ks * 8 + tig;
        uint32_t a[2][4];
#pragma unroll
        for (int i = 0; i < 2; i++) {
            const int r = warpM * 32 + i * 16 + gID;
            if (FROM_TF32) {
                a[i][0] = sA_t[r * SA_PAD + k0 + tig];
                a[i][1] = sA_t[(r + 8) * SA_PAD + k0 + tig];
                a[i][2] = sA_t[r * SA_PAD + k0 + tig + 4];
                a[i][3] = sA_t[(r + 8) * SA_PAD + k0 + tig + 4];
            } else {
                a[i][0] = f2tf32(sA_f[r * SA_PAD + k0 + tig]);
                a[i][1] = f2tf32(sA_f[(r + 8) * SA_PAD + k0 + tig]);
                a[i][2] = f2tf32(sA_f[r * SA_PAD + k0 + tig + 4]);
                a[i][3] = f2tf32(sA_f[(r + 8) * SA_PAD + k0 + tig + 4]);
            }
        }
        uint32_t b[4][2];
#pragma unroll
        for (int j = 0; j < 4; j++) {
            const int cc = warpN * 32 + j * 8 + gID;
            b[j][0] = sB[bk * SB_PAD + cc];
            b[j][1] = sB[(bk + 4) * SB_PAD + cc];
        }
#pragma unroll
        for (int i = 0; i < 2; i++)
#pragma unroll
            for (int j = 0; j < 4; j++)
                mma_tf32(&acc[(i * 4 + j) * 4], a[i], b[j]);
    }
}

#define STAGE(s, ACC, FT)                                                          \
    {                                                                              \
        if ((s) + 1 < 12) {                                                        \
            issue_load(sb_addr[((s) + 1) & 1], stage_gbase((s) + 1), tid);         \
            asm volatile("cp.async.commit_group;");                                \
        }                                                                          \
        asm volatile("cp.async.wait_group %0;" :: "n"((((s) + 1) < 12) ? 1 : 0));  \
        __syncthreads();                                                           \
        compute_half<FT>(ACC, sA1, sA2, sBbuf[(s) & 1], ((s) & 1) * 64,            \
                         warpM, warpN, gID, tig);                                  \
        __syncthreads();                                                           \
    }

__global__ __launch_bounds__(256, 1)
void fused_gru_kernel(const float* __restrict__ atom_state,
                      const float* __restrict__ msgs,
                      const float* __restrict__ bias,
                      float* __restrict__ out) {
    extern __shared__ unsigned char smem_raw[];
    uint32_t* sA1 = reinterpret_cast<uint32_t*>(smem_raw);
    float*    sA2 = reinterpret_cast<float*>(smem_raw + SA_BYTES);
    uint32_t* sBbuf[2];
    sBbuf[0] = reinterpret_cast<uint32_t*>(smem_raw + 2 * SA_BYTES);
    sBbuf[1] = reinterpret_cast<uint32_t*>(smem_raw + 2 * SA_BYTES + SBBUF_BYTES);
    uint32_t sb_addr[2];
    sb_addr[0] = (uint32_t)__cvta_generic_to_shared(sBbuf[0]);
    sb_addr[1] = (uint32_t)__cvta_generic_to_shared(sBbuf[1]);

    const int tid   = threadIdx.x;
    const int lane  = tid & 31;
    const int warp  = tid >> 5;
    const int warpM = warp >> 2;   // 0..1
    const int warpN = warp & 3;    // 0..3
    const int gID   = lane >> 2;   // 0..7
    const int tig   = lane & 3;    // 0..3
    const int row0  = blockIdx.x * 64;

    // prefetch B stage 0 immediately
    issue_load(sb_addr[0], stage_gbase(0), tid);
    asm volatile("cp.async.commit_group;");

    // ---- gather: each warp aggregates messages for its 8 rows into sA1 ----
    {
        const int rowbase = row0 + warp * 8;
        int v = 0;
        if (lane < 9) v = __ldg(&g_off[rowbase + lane]);
        int start[8], cnt[8];
#pragma unroll
        for (int r = 0; r < 8; r++) {
            const int s = __shfl_sync(0xffffffff, v, r);
            const int e = __shfl_sync(0xffffffff, v, r + 1);
            start[r] = s;
            cnt[r]   = e - s;
        }
        int maxcnt = 0;
#pragma unroll
        for (int r = 0; r < 8; r++) maxcnt = max(maxcnt, cnt[r]);

        float4 acc[8];
#pragma unroll
        for (int r = 0; r < 8; r++) acc[r] = make_float4(0.f, 0.f, 0.f, 0.f);

        const float4* m4 = reinterpret_cast<const float4*>(msgs);
        for (int j = 0; j < maxcnt; j++) {
#pragma unroll
            for (int r = 0; r < 8; r++) {
                if (j < cnt[r]) {
                    const int eid = __ldg(&g_edge[start[r] + j]);
                    const float4 m = __ldg(&m4[(size_t)eid * 32 + lane]);
                    acc[r].x += m.x; acc[r].y += m.y;
                    acc[r].z += m.z; acc[r].w += m.w;
                }
            }
        }
#pragma unroll
        for (int r = 0; r < 8; r++) {
            uint4 t = make_uint4(f2tf32(acc[r].x), f2tf32(acc[r].y),
                                 f2tf32(acc[r].z), f2tf32(acc[r].w));
            *reinterpret_cast<uint4*>(&sA1[(warp * 8 + r) * SA_PAD + lane * 4]) = t;
        }
    }

    // ---- h tile -> exact f32 smem ----
#pragma unroll
    for (int idx = tid; idx < 64 * 32; idx += 256) {
        const int r  = idx >> 5;
        const int c4 = (idx & 31) << 2;
        float4 vh = *reinterpret_cast<const float4*>(
            &atom_state[(size_t)(row0 + r) * DD + c4]);
        *reinterpret_cast<float4*>(&sA2[r * SA_PAD + c4]) = vh;
    }

    // ---- GEMM 1: X = agg @ W  (stages 0..5) ----
    float X[3][32];
#pragma unroll
    for (int q = 0; q < 3; q++)
#pragma unroll
        for (int u = 0; u < 32; u++) X[q][u] = 0.f;

    STAGE(0, X[0], true)
    STAGE(1, X[0], true)
    STAGE(2, X[1], true)
    STAGE(3, X[1], true)
    STAGE(4, X[2], true)
    STAGE(5, X[2], true)

    float Hc[32];

    // ---- GEMM 2 chunk r (U q=1), stages 6,7 ----
#pragma unroll
    for (int u = 0; u < 32; u++) Hc[u] = 0.f;
    STAGE(6, Hc, false)
    STAGE(7, Hc, false)
#pragma unroll
    for (int i = 0; i < 2; i++)
#pragma unroll
        for (int j = 0; j < 4; j++)
#pragma unroll
            for (int c = 0; c < 4; c++) {
                const int u   = (i * 4 + j) * 4 + c;
                const int col = warpN * 32 + j * 8 + tig * 2 + (c & 1);
                const float v = X[1][u] + bias[128 + col] + Hc[u] + bias[384 + 128 + col];
                X[1][u] = sigmoidf_fast(v);          // r gate
            }

    // ---- GEMM 2 chunk z (U q=0), stages 8,9 ----
#pragma unroll
    for (int u = 0; u < 32; u++) Hc[u] = 0.f;
    STAGE(8, Hc, false)
    STAGE(9, Hc, false)
#pragma unroll
    for (int i = 0; i < 2; i++)
#pragma unroll
        for (int j = 0; j < 4; j++)
#pragma unroll
            for (int c = 0; c < 4; c++) {
                const int u   = (i * 4 + j) * 4 + c;
                const int col = warpN * 32 + j * 8 + tig * 2 + (c & 1);
                const float v = X[0][u] + bias[col] + Hc[u] + bias[384 + col];
                X[0][u] = sigmoidf_fast(v);          // z gate
            }

    // ---- GEMM 2 chunk hh (U q=2), stages 10,11 + combine + store ----
#pragma unroll
    for (int u = 0; u < 32; u++) Hc[u] = 0.f;
    STAGE(10, Hc, false)
    STAGE(11, Hc, false)
#pragma unroll
    for (int i = 0; i < 2; i++)
#pragma unroll
        for (int j = 0; j < 4; j++)
#pragma unroll
            for (int c = 0; c < 4; c++) {
                const int u   = (i * 4 + j) * 4 + c;
                const int rt  = warpM * 32 + i * 16 + gID + ((c >> 1) << 3);
                const int col = warpN * 32 + j * 8 + tig * 2 + (c & 1);
                const float rh = Hc[u] + bias[384 + 256 + col];
                const float hh = tanh_safe(X[2][u] + bias[256 + col] + X[1][u] * rh);
                const float z  = X[0][u];
                const float h  = sA2[rt * SA_PAD + col];   // exact fp32 h
                out[(size_t)(row0 + rt) * DD + col] = z * h + (1.0f - z) * hh;
            }
}

// ---------------------------------------------------------------------------
// launch
// ---------------------------------------------------------------------------
extern "C" void kernel_launch(void* const* d_in, const int* in_sizes, int n_in,
                              void* d_out, int out_size) {
    const float* atom_state = (const float*)d_in[0];
    const float* messages   = (const float*)d_in[1];
    const int*   conn       = (const int*)d_in[2];
    const float* Wk         = (const float*)d_in[3];
    const float* Uk         = (const float*)d_in[4];
    const float* bias       = (const float*)d_in[5];
    float*       out        = (float*)d_out;
    (void)in_sizes; (void)n_in; (void)out_size;

    cudaFuncSetAttribute(fused_gru_kernel,
                         cudaFuncAttributeMaxDynamicSharedMemorySize, SMEM_BYTES);

    void* cnt_ptr = nullptr;
    cudaGetSymbolAddress(&cnt_ptr, g_cnt);
    cudaMemsetAsync(cnt_ptr, 0, MM * sizeof(int));   // defensive; fill self-zeroes

    hist_kernel<<<NEDGE / 256, 256>>>(conn);
    scan_kernel<<<1, 1024>>>();
    fill_kernel<<<NEDGE / 256, 256>>>(conn);
    convert_B_kernel<<<96, 256>>>(Wk, Uk);
    fused_gru_kernel<<<MM / 64, 256, SMEM_BYTES>>>(atom_state, messages, bias, out);
}

// round 6
// speedup vs baseline: 1.8555x; 1.8555x over previous
#include <cuda_runtime.h>
#include <cstdint>

// Problem shape (fixed): B=32, N=4096, E=8192, D=128
#define BB   32
#define NN   4096
#define EE   8192
#define DD   128
#define MM   (BB * NN)          // 131072 rows
#define NEDGE (BB * EE)         // 262144 edges

// device scratch: 64MB aggregation + 384KB fragment-major tf32 weight images
__device__ __align__(16) float    g_agg[(size_t)MM * DD];
__device__ __align__(16) uint32_t g_Btf[6 * 16384];   // 6 chunks x 64KB

// ---------------------------------------------------------------------------
// helpers
// ---------------------------------------------------------------------------
__device__ __forceinline__ uint32_t f2tf32(float x) {
    uint32_t r;
    asm("cvt.rna.tf32.f32 %0, %1;" : "=r"(r) : "f"(x));
    return r;
}
__device__ __forceinline__ float sigmoidf_fast(float x) {
    return 1.0f / (1.0f + __expf(-x));
}
__device__ __forceinline__ float tanh_safe(float x) {
    float e = __expf(-2.0f * fabsf(x));
    float t = (1.0f - e) / (1.0f + e);
    return copysignf(t, x);
}
__device__ __forceinline__ void mma_tf32(float* c, const uint32_t a[4], const uint32_t b[2]) {
    asm volatile(
        "mma.sync.aligned.m16n8k8.row.col.f32.tf32.tf32.f32 "
        "{%0,%1,%2,%3}, {%4,%5,%6,%7}, {%8,%9}, {%0,%1,%2,%3};\n"
        : "+f"(c[0]), "+f"(c[1]), "+f"(c[2]), "+f"(c[3])
        : "r"(a[0]), "r"(a[1]), "r"(a[2]), "r"(a[3]),
          "r"(b[0]), "r"(b[1]));
}
__device__ __forceinline__ void cp_async16(uint32_t saddr, const void* g) {
    asm volatile("cp.async.cg.shared.global [%0], [%1], 16;\n" :: "r"(saddr), "l"(g));
}

// ---------------------------------------------------------------------------
// kernel: scatter-add messages into g_agg (one warp per edge, red.v4)
// ---------------------------------------------------------------------------
__global__ void scatter_kernel(const float* __restrict__ msgs,
                               const int*   __restrict__ conn) {
    const int gwarp = (blockIdx.x * blockDim.x + threadIdx.x) >> 5;
    const int lane  = threadIdx.x & 31;
    if (gwarp >= NEDGE) return;
    const int tgt = __ldg(&conn[2 * gwarp + 1]);
    const int b   = gwarp >> 13;
    const float4 m = reinterpret_cast<const float4*>(msgs)[(size_t)gwarp * 32 + lane];
    float* dst = &g_agg[((size_t)b * NN + tgt) * DD + lane * 4];
    asm volatile("red.global.add.v4.f32 [%0], {%1, %2, %3, %4};"
                 :: "l"(dst), "f"(m.x), "f"(m.y), "f"(m.z), "f"(m.w) : "memory");
}

// ---------------------------------------------------------------------------
// kernel: build FRAGMENT-MAJOR tf32 weight images.
// Chunk exec order e: 0=W0(z) 1=W1(r) 2=W2(hh) 3=U1(r) 4=U0(z) 5=U2(hh)
// Within chunk: uint4 index iu = ((ks*4 + warpN)*2 + p)*32 + gID*4 + tig
//   components = { B[8ks+tig][C], B[8ks+tig+4][C], B[8ks+tig][C+8], B[8ks+tig+4][C+8] }
//   with C = warpN*32 + 16*p + gID ; B[k][c] = src[k*384 + q*128 + c]
// ---------------------------------------------------------------------------
__global__ void convert_B_kernel(const float* __restrict__ W,
                                 const float* __restrict__ U) {
    const int t = blockIdx.x * blockDim.x + threadIdx.x;   // 0..24575 uint4s
    if (t >= 6 * 4096) return;
    const int e   = t >> 12;
    const int iu  = t & 4095;
    const int tig = iu & 3;
    const int g   = (iu >> 2) & 7;
    const int p   = (iu >> 5) & 1;
    const int wN  = (iu >> 6) & 3;
    const int ks  = iu >> 8;
    int m, q;
    if (e < 3) { m = 0; q = e; }
    else       { m = 1; q = (e == 3) ? 1 : ((e == 4) ? 0 : 2); }
    const float* src = m ? U : W;
    const int k1 = ks * 8 + tig, k2 = k1 + 4;
    const int C  = wN * 32 + p * 16 + g;
    uint4 v;
    v.x = f2tf32(src[k1 * 384 + q * 128 + C]);
    v.y = f2tf32(src[k2 * 384 + q * 128 + C]);
    v.z = f2tf32(src[k1 * 384 + q * 128 + C + 8]);
    v.w = f2tf32(src[k2 * 384 + q * 128 + C + 8]);
    reinterpret_cast<uint4*>(g_Btf)[t] = v;
}

// ---------------------------------------------------------------------------
// fused dual-GEMM + GRU gates (fragment-major smem, cp.async double buffer)
// smem: sAf 32K | sB0 32K | sB1 32K | sA2 raw h 33792B | bias 3072B
// ---------------------------------------------------------------------------
#define SM_AF   0
#define SM_B0   32768
#define SM_B1   65536
#define SM_A2   98304
#define SM_BIAS (98304 + 33792)
#define SMEM_TOTAL (SM_BIAS + 3072)
#define PITCH 132

__device__ __forceinline__ void load_stage(uint32_t buf, int s, int tid) {
    const uint32_t off = (uint32_t)((s >> 1) * 16384 + (s & 1) * 8192);
#pragma unroll
    for (int i = 0; i < 8; i++) {
        const int e = tid + i * 256;                 // 0..2047 (x16B)
        cp_async16(buf + (uint32_t)e * 16, &g_Btf[off + e * 4]);
    }
}

template <bool RAW>
__device__ __forceinline__ void build_A(unsigned char* smem, const float* __restrict__ src,
                                        int row0, int tid) {
    uint32_t* sAf = reinterpret_cast<uint32_t*>(smem + SM_AF);
    float*    sA2 = reinterpret_cast<float*>(smem + SM_A2);
#pragma unroll
    for (int it = 0; it < 8; it++) {
        const int idx = tid + it * 256;              // 0..2047
        const int row = idx >> 5;
        const int c4  = (idx & 31) << 2;
        float4 v = *reinterpret_cast<const float4*>(&src[(size_t)(row0 + row) * DD + c4]);
        if (RAW) *reinterpret_cast<float4*>(&sA2[row * PITCH + c4]) = v;
        const int wm = row >> 5, rl = row & 31;
        const int cr = (rl >> 3) & 1, ii = (rl >> 4) & 1, g = rl & 7;
        const int ks = c4 >> 3, ch = (c4 >> 2) & 1;
        const int comp = ch * 2 + cr;
        const int base = (((ks * 2 + wm) * 2 + ii) * 32 + g * 4) * 4 + comp;
        sAf[base + 0 * 4] = f2tf32(v.x);
        sAf[base + 1 * 4] = f2tf32(v.y);
        sAf[base + 2 * 4] = f2tf32(v.z);
        sAf[base + 3 * 4] = f2tf32(v.w);
    }
}

__device__ __forceinline__ void compute_half(float* __restrict__ acc,   // [32]
                                             const uint4* __restrict__ sAf4,
                                             const uint4* __restrict__ sB4,
                                             int kb8, int wm, int wN, int lane) {
#pragma unroll
    for (int ks = 0; ks < 8; ks++) {
        const int ksg = kb8 + ks;
        const uint4 av0 = sAf4[((ksg * 2 + wm) * 2 + 0) * 32 + lane];
        const uint4 av1 = sAf4[((ksg * 2 + wm) * 2 + 1) * 32 + lane];
        const uint4 bv0 = sB4[((ks * 4 + wN) * 2 + 0) * 32 + lane];
        const uint4 bv1 = sB4[((ks * 4 + wN) * 2 + 1) * 32 + lane];
        const uint32_t a0[4] = {av0.x, av0.y, av0.z, av0.w};
        const uint32_t a1[4] = {av1.x, av1.y, av1.z, av1.w};
        uint32_t b[2];
        b[0] = bv0.x; b[1] = bv0.y; mma_tf32(acc + 0,  a0, b); mma_tf32(acc + 16, a1, b);
        b[0] = bv0.z; b[1] = bv0.w; mma_tf32(acc + 4,  a0, b); mma_tf32(acc + 20, a1, b);
        b[0] = bv1.x; b[1] = bv1.y; mma_tf32(acc + 8,  a0, b); mma_tf32(acc + 24, a1, b);
        b[0] = bv1.z; b[1] = bv1.w; mma_tf32(acc + 12, a0, b); mma_tf32(acc + 28, a1, b);
    }
}

#define STAGE(s, ACC)                                                              \
    {                                                                              \
        if ((s) + 1 < 12) {                                                        \
            load_stage(sb_addr[((s) + 1) & 1], (s) + 1, tid);                      \
            asm volatile("cp.async.commit_group;");                                \
        }                                                                          \
        asm volatile("cp.async.wait_group %0;" :: "n"((((s) + 1) < 12) ? 1 : 0));  \
        __syncthreads();                                                           \
        compute_half(ACC, sAf4, ((s) & 1) ? sB1_4 : sB0_4, ((s) & 1) * 8,          \
                     warpM, warpN, lane);                                          \
        __syncthreads();                                                           \
    }

__global__ __launch_bounds__(256, 1)
void fused_gru_kernel(const float* __restrict__ atom_state,
                      const float* __restrict__ bias,
                      float* __restrict__ out) {
    extern __shared__ unsigned char smem[];
    const uint4* sAf4  = reinterpret_cast<const uint4*>(smem + SM_AF);
    const uint4* sB0_4 = reinterpret_cast<const uint4*>(smem + SM_B0);
    const uint4* sB1_4 = reinterpret_cast<const uint4*>(smem + SM_B1);
    float* sA2   = reinterpret_cast<float*>(smem + SM_A2);
    float* sBias = reinterpret_cast<float*>(smem + SM_BIAS);
    float* sStage = reinterpret_cast<float*>(smem + SM_B0);  // dead after stage 11
    uint32_t sb_addr[2];
    sb_addr[0] = (uint32_t)__cvta_generic_to_shared(smem + SM_B0);
    sb_addr[1] = (uint32_t)__cvta_generic_to_shared(smem + SM_B1);

    const int tid   = threadIdx.x;
    const int lane  = tid & 31;
    const int warp  = tid >> 5;
    const int warpM = warp >> 2;   // 0..1
    const int warpN = warp & 3;    // 0..3
    const int gID   = lane >> 2;   // 0..7
    const int tig   = lane & 3;    // 0..3
    const int row0  = blockIdx.x * 64;

    // prefetch B stage 0 first
    load_stage(sb_addr[0], 0, tid);
    asm volatile("cp.async.commit_group;");

    // A = agg (fragment-major tf32); bias -> smem
    build_A<false>(smem, g_agg, row0, tid);
    if (tid < 192) {
        float4 v = *reinterpret_cast<const float4*>(&bias[tid * 4]);
        *reinterpret_cast<float4*>(&sBias[tid * 4]) = v;
    }

    // ---- GEMM 1: X = agg @ W (stages 0..5) ----
    float X[3][32];
#pragma unroll
    for (int q = 0; q < 3; q++)
#pragma unroll
        for (int u = 0; u < 32; u++) X[q][u] = 0.f;

    STAGE(0, X[0])
    STAGE(1, X[0])
    STAGE(2, X[1])
    STAGE(3, X[1])
    STAGE(4, X[2])
    STAGE(5, X[2])

    // rebuild A with h (raw copy kept for epilogue)
    build_A<true>(smem, atom_state, row0, tid);
    __syncthreads();

    float Hc[32];

    // ---- U1 -> r gate (stages 6,7) ----
#pragma unroll
    for (int u = 0; u < 32; u++) Hc[u] = 0.f;
    STAGE(6, Hc)
    STAGE(7, Hc)
#pragma unroll
    for (int i = 0; i < 2; i++)
#pragma unroll
        for (int j = 0; j < 4; j++)
#pragma unroll
            for (int c = 0; c < 4; c++) {
                const int u   = (i * 4 + j) * 4 + c;
                const int col = warpN * 32 + j * 8 + tig * 2 + (c & 1);
                const float v = X[1][u] + sBias[128 + col] + Hc[u] + sBias[384 + 128 + col];
                X[1][u] = sigmoidf_fast(v);          // r gate
            }

    // ---- U0 -> z gate (stages 8,9) ----
#pragma unroll
    for (int u = 0; u < 32; u++) Hc[u] = 0.f;
    STAGE(8, Hc)
    STAGE(9, Hc)
#pragma unroll
    for (int i = 0; i < 2; i++)
#pragma unroll
        for (int j = 0; j < 4; j++)
#pragma unroll
            for (int c = 0; c < 4; c++) {
                const int u   = (i * 4 + j) * 4 + c;
                const int col = warpN * 32 + j * 8 + tig * 2 + (c & 1);
                const float v = X[0][u] + sBias[col] + Hc[u] + sBias[384 + col];
                X[0][u] = sigmoidf_fast(v);          // z gate
            }

    // ---- U2 -> hh, combine (stages 10,11) ----
#pragma unroll
    for (int u = 0; u < 32; u++) Hc[u] = 0.f;
    STAGE(10, Hc)
    STAGE(11, Hc)
#pragma unroll
    for (int i = 0; i < 2; i++)
#pragma unroll
        for (int j = 0; j < 4; j++)
#pragma unroll
            for (int c = 0; c < 4; c++) {
                const int u   = (i * 4 + j) * 4 + c;
                const int rt  = warpM * 32 + i * 16 + gID + ((c >> 1) << 3);
                const int col = warpN * 32 + j * 8 + tig * 2 + (c & 1);
                const float rh = Hc[u] + sBias[384 + 256 + col];
                const float hh = tanh_safe(X[2][u] + sBias[256 + col] + X[1][u] * rh);
                const float z  = X[0][u];
                const float h  = sA2[rt * PITCH + col];   // exact fp32 h
                sStage[rt * PITCH + col] = z * h + (1.0f - z) * hh;
            }
    __syncthreads();

    // coalesced float4 store
#pragma unroll
    for (int it = 0; it < 8; it++) {
        const int idx = tid + it * 256;              // 0..2047
        const int row = idx >> 5;
        const int c4  = (idx & 31) << 2;
        float4 v = *reinterpret_cast<const float4*>(&sStage[row * PITCH + c4]);
        *reinterpret_cast<float4*>(&out[(size_t)(row0 + row) * DD + c4]) = v;
    }
}

// ---------------------------------------------------------------------------
// launch
// ---------------------------------------------------------------------------
extern "C" void kernel_launch(void* const* d_in, const int* in_sizes, int n_in,
                              void* d_out, int out_size) {
    const float* atom_state = (const float*)d_in[0];
    const float* messages   = (const float*)d_in[1];
    const int*   conn       = (const int*)d_in[2];
    const float* Wk         = (const float*)d_in[3];
    const float* Uk         = (const float*)d_in[4];
    const float* bias       = (const float*)d_in[5];
    float*       out        = (float*)d_out;
    (void)in_sizes; (void)n_in; (void)out_size;

    cudaFuncSetAttribute(fused_gru_kernel,
                         cudaFuncAttributeMaxDynamicSharedMemorySize, SMEM_TOTAL);

    void* agg_ptr = nullptr;
    cudaGetSymbolAddress(&agg_ptr, g_agg);
    cudaMemsetAsync(agg_ptr, 0, (size_t)MM * DD * sizeof(float));

    convert_B_kernel<<<96, 256>>>(Wk, Uk);
    scatter_kernel<<<NEDGE / 8, 256>>>(messages, conn);
    fused_gru_kernel<<<MM / 64, 256, SMEM_TOTAL>>>(atom_state, bias, out);
}